// round 6
// baseline (speedup 1.0000x reference)
#include <cuda_runtime.h>

#define C 128
#define MAXN 50000
#define MAXE 1600000

// Scratch (no cudaMalloc allowed)
__device__ __align__(16) float g_h [MAXN * C];   // current node features
__device__ __align__(16) float g_hw[MAXN * C];   // h @ W   (also P = h @ W_top)
__device__ __align__(16) float g_q [MAXN * C];   // Q = h @ W_bot
__device__ int   g_deg[MAXN];
__device__ float g_dis[MAXN];
__device__ int   g_ptr[MAXN + 1];
__device__ int   g_cur[MAXN];
__device__ int   g_src[MAXE];

// ---------------------------------------------------------------------------
// CSR build
// ---------------------------------------------------------------------------
__global__ void k_init(int N) {
    int i = blockIdx.x * blockDim.x + threadIdx.x;
    if (i < N) { g_deg[i] = 1; g_cur[i] = 0; }   // deg starts at 1 (self loop)
}

__global__ void k_count(const int* __restrict__ col, int E) {
    int e = blockIdx.x * blockDim.x + threadIdx.x;
    if (e < E) atomicAdd(&g_deg[col[e]], 1);
}

// single-block scan over in-degrees (deg-1), also computes dis = rsqrt(deg)
__global__ void k_scan(int N) {
    const int T = 1024;
    int tid = threadIdx.x;
    int chunk = (N + T - 1) / T;
    int beg = tid * chunk;
    int end = min(beg + chunk, N);
    int s = 0;
    for (int i = beg; i < end; i++) s += g_deg[i] - 1;
    __shared__ int sums[T];
    sums[tid] = s;
    __syncthreads();
    for (int off = 1; off < T; off <<= 1) {
        int v = (tid >= off) ? sums[tid - off] : 0;
        __syncthreads();
        sums[tid] += v;
        __syncthreads();
    }
    int run = (tid > 0) ? sums[tid - 1] : 0;
    for (int i = beg; i < end; i++) {
        g_ptr[i] = run;
        int d = g_deg[i];
        run += d - 1;
        g_dis[i] = rsqrtf((float)d);
    }
    if (tid == T - 1) g_ptr[N] = sums[T - 1];
}

__global__ void k_fill(const int* __restrict__ row, const int* __restrict__ col, int E) {
    int e = blockIdx.x * blockDim.x + threadIdx.x;
    if (e < E) {
        int c = col[e];
        int pos = atomicAdd(&g_cur[c], 1);
        g_src[g_ptr[c] + pos] = row[e];
    }
}

// ---------------------------------------------------------------------------
// GEMM: Out[M,128] = A[M,128] @ W[128,128]   (W row-major [k][c])
// 64 rows x 128 cols per 256-thread block; 8x4 register tile per thread.
// ---------------------------------------------------------------------------
__global__ __launch_bounds__(256, 2)
void k_gemm(const float* __restrict__ A, const float* __restrict__ W,
            float* __restrict__ Out, int M) {
    extern __shared__ float smem[];
    float* sW = smem;          // 128*128
    float* sA = smem + 16384;  // 64*128
    int tid = threadIdx.x;

    const float4* W4 = (const float4*)W;
    float4* sW4 = (float4*)sW;
    #pragma unroll
    for (int i = tid; i < 4096; i += 256) sW4[i] = W4[i];

    int m0 = blockIdx.x * 64;
    float4* sA4 = (float4*)sA;
    const float4* A4 = (const float4*)A;
    for (int i = tid; i < 2048; i += 256) {
        int r = i >> 5, c = i & 31;
        int gm = m0 + r;
        sA4[i] = (gm < M) ? A4[(size_t)gm * 32 + c] : make_float4(0.f, 0.f, 0.f, 0.f);
    }
    __syncthreads();

    int ty = tid >> 5, tx = tid & 31;
    float acc[8][4];
    #pragma unroll
    for (int e = 0; e < 8; e++)
        #pragma unroll
        for (int j = 0; j < 4; j++) acc[e][j] = 0.f;

    #pragma unroll 2
    for (int k = 0; k < 128; k += 4) {
        float4 w0 = *(float4*)&sW[(k + 0) * 128 + tx * 4];
        float4 w1 = *(float4*)&sW[(k + 1) * 128 + tx * 4];
        float4 w2 = *(float4*)&sW[(k + 2) * 128 + tx * 4];
        float4 w3 = *(float4*)&sW[(k + 3) * 128 + tx * 4];
        #pragma unroll
        for (int e = 0; e < 8; e++) {
            float4 u = *(float4*)&sA[(ty * 8 + e) * 128 + k];
            acc[e][0] += u.x * w0.x + u.y * w1.x + u.z * w2.x + u.w * w3.x;
            acc[e][1] += u.x * w0.y + u.y * w1.y + u.z * w2.y + u.w * w3.y;
            acc[e][2] += u.x * w0.z + u.y * w1.z + u.z * w2.z + u.w * w3.z;
            acc[e][3] += u.x * w0.w + u.y * w1.w + u.z * w2.w + u.w * w3.w;
        }
    }
    #pragma unroll
    for (int e = 0; e < 8; e++) {
        int gm = m0 + ty * 8 + e;
        if (gm < M)
            *(float4*)&Out[(size_t)gm * 128 + tx * 4] =
                make_float4(acc[e][0], acc[e][1], acc[e][2], acc[e][3]);
    }
}

// ---------------------------------------------------------------------------
// Aggregation: one warp per node.
// h_new[i] = relu( dis[i]*sum_{src in CSR(i)} dis[src]*hw[src]
//                  + dis[i]^2*hw[i] + b  (+ h[i] if residual) )
// ---------------------------------------------------------------------------
__global__ void k_agg(const float* __restrict__ hw, const float* __restrict__ bias,
                      int N, int residual) {
    int warp = (blockIdx.x * blockDim.x + threadIdx.x) >> 5;
    int lane = threadIdx.x & 31;
    if (warp >= N) return;
    int beg = g_ptr[warp], end = g_ptr[warp + 1];
    float ax = 0.f, ay = 0.f, az = 0.f, aw = 0.f;
    int j = beg;
    for (; j + 1 < end; j += 2) {
        int s0 = g_src[j], s1 = g_src[j + 1];
        float n0 = g_dis[s0], n1 = g_dis[s1];
        float4 v0 = *(const float4*)&hw[(size_t)s0 * 128 + lane * 4];
        float4 v1 = *(const float4*)&hw[(size_t)s1 * 128 + lane * 4];
        ax += n0 * v0.x + n1 * v1.x;
        ay += n0 * v0.y + n1 * v1.y;
        az += n0 * v0.z + n1 * v1.z;
        aw += n0 * v0.w + n1 * v1.w;
    }
    if (j < end) {
        int s = g_src[j];
        float n = g_dis[s];
        float4 v = *(const float4*)&hw[(size_t)s * 128 + lane * 4];
        ax += n * v.x; ay += n * v.y; az += n * v.z; aw += n * v.w;
    }
    float di = g_dis[warp];
    float sc = di * di;
    float4 sv = *(const float4*)&hw[(size_t)warp * 128 + lane * 4];
    ax = ax * di + sv.x * sc;
    ay = ay * di + sv.y * sc;
    az = az * di + sv.z * sc;
    aw = aw * di + sv.w * sc;
    float4 b = *(const float4*)&bias[lane * 4];
    ax += b.x; ay += b.y; az += b.z; aw += b.w;
    if (residual) {
        float4 hv = *(const float4*)&g_h[(size_t)warp * 128 + lane * 4];
        ax += hv.x; ay += hv.y; az += hv.z; aw += hv.w;
    }
    ax = fmaxf(ax, 0.f); ay = fmaxf(ay, 0.f);
    az = fmaxf(az, 0.f); aw = fmaxf(aw, 0.f);
    *(float4*)&g_h[(size_t)warp * 128 + lane * 4] = make_float4(ax, ay, az, aw);
}

// ---------------------------------------------------------------------------
// Edge MLP: per edge e
//   u = relu(P[src] + Q[dst] + b0)          (fc0, factorized)
//   v = relu(u @ fc1_W + b1)
//   out = v . fc2_w + b2
// 64 edges per 256-thread block. fc1_W + u tile in smem, 8x4 reg tile.
// ---------------------------------------------------------------------------
#define USTRIDE 132

__global__ __launch_bounds__(256, 2)
void k_edge(const int* __restrict__ row, const int* __restrict__ col,
            const float* __restrict__ b0, const float* __restrict__ W1,
            const float* __restrict__ b1, const float* __restrict__ w2,
            const float* __restrict__ b2, float* __restrict__ out, int E) {
    extern __shared__ float smem[];
    float* sW = smem;           // 128*128 = 16384 floats
    float* sU = smem + 16384;   // 64 * USTRIDE floats
    int tid = threadIdx.x;

    const float4* W4 = (const float4*)W1;
    float4* sW4 = (float4*)sW;
    #pragma unroll
    for (int i = tid; i < 4096; i += 256) sW4[i] = W4[i];

    int e0 = blockIdx.x * 64;
    {
        int le = tid >> 2;       // local edge 0..63
        int seg = tid & 3;       // 4 threads cooperate per edge row
        int e = e0 + le;
        if (e < E) {
            int s = row[e], d = col[e];
            const float4* Pr = (const float4*)&g_hw[(size_t)s * 128];
            const float4* Qr = (const float4*)&g_q[(size_t)d * 128];
            const float4* B = (const float4*)b0;
            #pragma unroll
            for (int i = 0; i < 8; i++) {
                int c4 = i * 4 + seg;            // contiguous 64B per 4-thread group
                float4 p = Pr[c4], q = Qr[c4], b = B[c4];
                float4 u;
                u.x = fmaxf(p.x + q.x + b.x, 0.f);
                u.y = fmaxf(p.y + q.y + b.y, 0.f);
                u.z = fmaxf(p.z + q.z + b.z, 0.f);
                u.w = fmaxf(p.w + q.w + b.w, 0.f);
                *(float4*)&sU[le * USTRIDE + c4 * 4] = u;
            }
        }
    }
    __syncthreads();

    int ty = tid >> 5, tx = tid & 31;
    float acc[8][4];
    #pragma unroll
    for (int e = 0; e < 8; e++)
        #pragma unroll
        for (int j = 0; j < 4; j++) acc[e][j] = 0.f;

    #pragma unroll 2
    for (int k = 0; k < 128; k += 4) {
        float4 w0 = *(float4*)&sW[(k + 0) * 128 + tx * 4];
        float4 w1 = *(float4*)&sW[(k + 1) * 128 + tx * 4];
        float4 w2r = *(float4*)&sW[(k + 2) * 128 + tx * 4];
        float4 w3 = *(float4*)&sW[(k + 3) * 128 + tx * 4];
        #pragma unroll
        for (int e = 0; e < 8; e++) {
            float4 u = *(float4*)&sU[(ty * 8 + e) * USTRIDE + k];
            acc[e][0] += u.x * w0.x + u.y * w1.x + u.z * w2r.x + u.w * w3.x;
            acc[e][1] += u.x * w0.y + u.y * w1.y + u.z * w2r.y + u.w * w3.y;
            acc[e][2] += u.x * w0.z + u.y * w1.z + u.z * w2r.z + u.w * w3.z;
            acc[e][3] += u.x * w0.w + u.y * w1.w + u.z * w2r.w + u.w * w3.w;
        }
    }

    float4 bv = ((const float4*)b1)[tx];
    float4 f2 = ((const float4*)w2)[tx];
    float bias2 = b2[0];
    #pragma unroll
    for (int e = 0; e < 8; e++) {
        float r = fmaxf(acc[e][0] + bv.x, 0.f) * f2.x
                + fmaxf(acc[e][1] + bv.y, 0.f) * f2.y
                + fmaxf(acc[e][2] + bv.z, 0.f) * f2.z
                + fmaxf(acc[e][3] + bv.w, 0.f) * f2.w;
        #pragma unroll
        for (int off = 16; off; off >>= 1)
            r += __shfl_down_sync(0xffffffffu, r, off);
        if (tx == 0) {
            int ee = e0 + ty * 8 + e;
            if (ee < E) out[ee] = r + bias2;
        }
    }
}

// ---------------------------------------------------------------------------
extern "C" void kernel_launch(void* const* d_in, const int* in_sizes, int n_in,
                              void* d_out, int out_size) {
    const float* x       = (const float*)d_in[0];
    const int*   ei      = (const int*)  d_in[1];
    const float* convs_W = (const float*)d_in[2];
    const float* convs_b = (const float*)d_in[3];
    const float* fc0_W   = (const float*)d_in[4];
    const float* fc0_b   = (const float*)d_in[5];
    const float* fc1_W   = (const float*)d_in[6];
    const float* fc1_b   = (const float*)d_in[7];
    const float* fc2_W   = (const float*)d_in[8];
    const float* fc2_b   = (const float*)d_in[9];
    float* out = (float*)d_out;

    int N = in_sizes[0] / C;
    int E = in_sizes[1] / 2;
    int n_layers = in_sizes[2] / (C * C);
    const int* row = ei;
    const int* col = ei + E;

    const int SMEM_GEMM = (16384 + 8192) * 4;           // 96 KB
    const int SMEM_EDGE = (16384 + 64 * USTRIDE) * 4;   // ~97 KB
    cudaFuncSetAttribute(k_gemm, cudaFuncAttributeMaxDynamicSharedMemorySize, SMEM_GEMM);
    cudaFuncSetAttribute(k_edge, cudaFuncAttributeMaxDynamicSharedMemorySize, SMEM_EDGE);

    float *p_h, *p_hw, *p_q;
    cudaGetSymbolAddress((void**)&p_h,  g_h);
    cudaGetSymbolAddress((void**)&p_hw, g_hw);
    cudaGetSymbolAddress((void**)&p_q,  g_q);

    // CSR build (per-launch; required since no state may persist)
    k_init <<<(N + 255) / 256, 256>>>(N);
    k_count<<<(E + 255) / 256, 256>>>(col, E);
    k_scan <<<1, 1024>>>(N);
    k_fill <<<(E + 255) / 256, 256>>>(row, col, E);

    int gb = (N + 63) / 64;
    int ab = (N * 32 + 255) / 256;

    // layer 0 (input = x, no residual)
    k_gemm<<<gb, 256, SMEM_GEMM>>>(x, convs_W, p_hw, N);
    k_agg <<<ab, 256>>>(p_hw, convs_b, N, 0);

    // layers 1..L-1 (residual)
    for (int l = 1; l < n_layers; l++) {
        k_gemm<<<gb, 256, SMEM_GEMM>>>(p_h, convs_W + (size_t)l * C * C, p_hw, N);
        k_agg <<<ab, 256>>>(p_hw, convs_b + (size_t)l * C, N, 1);
    }

    // fc0 factorization: P = h @ W_top (-> g_hw), Q = h @ W_bot (-> g_q)
    k_gemm<<<gb, 256, SMEM_GEMM>>>(p_h, fc0_W,            p_hw, N);
    k_gemm<<<gb, 256, SMEM_GEMM>>>(p_h, fc0_W + C * C,    p_q,  N);

    // fused per-edge MLP (fc0-combine + relu + fc1 + relu + fc2)
    k_edge<<<(E + 63) / 64, 256, SMEM_EDGE>>>(row, col, fc0_b, fc1_W, fc1_b,
                                              fc2_W, fc2_b, out, E);
}